// round 12
// baseline (speedup 1.0000x reference)
#include <cuda_runtime.h>

#define BN_TOT 16384   // B*N = 4*4096
#define NPTS   4096
#define KK     40

typedef unsigned long long ull;

// ---------------- scratch (device globals; no allocation allowed) -------------
__device__ int      d_idx[BN_TOT * KK];
__device__ float    d_feats[BN_TOT * 192];   // [x1 | x2 | x3]
__device__ float    d_P[BN_TOT * 64];        // per-stage neighbor term (scaled)
__device__ float    d_cst[BN_TOT * 64];      // per-stage center term (affine folded)
__device__ float    d_h7[BN_TOT * 512];
__device__ float    d_h8[BN_TOT * 256];
__device__ unsigned d_gmax[4 * 1024];        // per-batch conv6 max (order-preserving uint)
__device__ float    d_wd3[64 * 64];          // W3[:,64:128]-W3[:,0:64]
__device__ float    d_wd5[64 * 64];
__device__ float    d_gterm[4 * 512];        // g @ W7[:, :1024]^T  per batch

__device__ __forceinline__ unsigned fkey(float f) {
    unsigned u = __float_as_uint(f);
    return (u & 0x80000000u) ? ~u : (u | 0x80000000u);
}
__device__ __forceinline__ float fdecode(unsigned k) {
    return (k & 0x80000000u) ? __uint_as_float(k ^ 0x80000000u) : __uint_as_float(~k);
}
__device__ __forceinline__ float lrelu(float v) { return v >= 0.f ? v : 0.2f * v; }

// packed fp32x2 FMA (Blackwell)
__device__ __forceinline__ ull fma2(ull a, ull b, ull c) {
    ull d;
    asm("fma.rn.f32x2 %0, %1, %2, %3;" : "=l"(d) : "l"(a), "l"(b), "l"(c));
    return d;
}
__device__ __forceinline__ ull mul2(ull a, ull b) {
    ull d;
    asm("mul.rn.f32x2 %0, %1, %2;" : "=l"(d) : "l"(a), "l"(b));
    return d;
}
__device__ __forceinline__ float red2(ull a) {
    float x, y;
    asm("mov.b64 {%0, %1}, %2;" : "=f"(x), "=f"(y) : "l"(a));
    return x + y;
}
__device__ __forceinline__ ull pack2(float x, float y) {
    ull d;
    asm("mov.b64 %0, {%1, %2};" : "=l"(d) : "f"(x), "f"(y));
    return d;
}

// ---------------- prep kernels ------------------------------------------------
__global__ void prep_w_kernel(const float* __restrict__ W3, const float* __restrict__ W5) {
    int t = blockIdx.x * blockDim.x + threadIdx.x;
    if (t < 4096) {
        int c = t >> 6, i = t & 63;
        d_wd3[t] = W3[c * 128 + 64 + i] - W3[c * 128 + i];
    } else if (t < 8192) {
        int u = t - 4096; int c = u >> 6, i = u & 63;
        d_wd5[u] = W5[c * 128 + 64 + i] - W5[c * 128 + i];
    }
}
__global__ void prep_g_kernel() {
    int t = blockIdx.x * blockDim.x + threadIdx.x;
    if (t < 4096) d_gmax[t] = 0u;
}

// stage1 P/C: P[q,c] = (W1lo[c]·xyz_q)*s1[c], C[q,c] = ((W1hi-W1lo)[c]·xyz_q)*s1[c]+b1[c]
__global__ void __launch_bounds__(256) prep1_kernel(
    const float* __restrict__ x, const float* __restrict__ W1,
    const float* __restrict__ s1, const float* __restrict__ b1) {
    int t = blockIdx.x * 256 + threadIdx.x;
    int q = t >> 6, c = t & 63;
    int b = q >> 12, n = q & 4095;
    const float* xb = x + b * 3 * NPTS;
    float cx = xb[n], cy = xb[NPTS + n], cz = xb[2 * NPTS + n];
    float w0 = W1[c * 6 + 0], w1 = W1[c * 6 + 1], w2 = W1[c * 6 + 2];
    float w3 = W1[c * 6 + 3], w4 = W1[c * 6 + 4], w5 = W1[c * 6 + 5];
    float s = s1[c];
    d_P[q * 64 + c]   = (w0 * cx + w1 * cy + w2 * cz) * s;
    d_cst[q * 64 + c] = ((w3 - w0) * cx + (w4 - w1) * cy + (w5 - w2) * cz) * s + b1[c];
}

// ---------------- KNN: radix top-40; match-aggregated atomics in pass 0 -------
__global__ void __launch_bounds__(128) knn_kernel(const float* __restrict__ x) {
    const int q = blockIdx.x;
    const int b = q >> 12, n = q & 4095;
    const int tid = threadIdx.x;
    __shared__ unsigned key[NPTS];
    __shared__ unsigned hist[256];
    __shared__ unsigned sc[2];
    __shared__ int cHi, cEq;

    const float* xb = x + b * 3 * NPTS;
    float cx = xb[n], cy = xb[NPTS + n], cz = xb[2 * NPTS + n];
    float xxi = cx * cx + cy * cy + cz * cz;

    for (int j = tid; j < NPTS; j += 128) {
        float px = xb[j], py = xb[NPTS + j], pz = xb[2 * NPTS + j];
        float dot = cx * px + cy * py + cz * pz;
        float xxj = px * px + py * py + pz * pz;
        float d = (2.f * dot - xxi) - xxj;   // = -||xi-xj||^2, larger = nearer
        key[j] = fkey(d);
    }

    unsigned prefix = 0, need = KK;
    for (int pass = 0; pass < 4; ++pass) {
        int shift = 24 - 8 * pass;
        unsigned himask = (pass == 0) ? 0u : (0xFFFFFFFFu << (shift + 8));
        for (int i2 = tid; i2 < 256; i2 += 128) hist[i2] = 0u;
        __syncthreads();
        if (pass == 0) {
            for (int j = tid; j < NPTS; j += 128) {
                int bucket = (int)(key[j] >> shift);
                unsigned mm = __match_any_sync(0xffffffffu, bucket);
                if ((tid & 31) == (__ffs(mm) - 1))
                    atomicAdd(&hist[bucket], (unsigned)__popc(mm));
            }
        } else {
            for (int j = tid; j < NPTS; j += 128) {
                unsigned k = key[j];
                if ((k & himask) == (prefix & himask))
                    atomicAdd(&hist[(k >> shift) & 255], 1u);
            }
        }
        __syncthreads();
        if (tid < 32) {
            unsigned part[8]; unsigned s = 0;
            #pragma unroll
            for (int r = 0; r < 8; r++) { part[r] = hist[255 - tid * 8 - r]; s += part[r]; }
            unsigned inc = s;
            #pragma unroll
            for (int o = 1; o < 32; o <<= 1) {
                unsigned v = __shfl_up_sync(0xffffffffu, inc, o);
                if (tid >= o) inc += v;
            }
            unsigned excl = inc - s;
            unsigned ball = __ballot_sync(0xffffffffu, (excl < need) && (need <= inc));
            int lane = __ffs(ball) - 1;
            if (tid == lane) {
                unsigned rem = need - excl, cacc = 0; int r = 0;
                for (; r < 8; r++) { if (cacc + part[r] >= rem) break; cacc += part[r]; }
                unsigned v = 255u - (unsigned)(tid * 8) - (unsigned)r;
                sc[0] = prefix | (v << shift);
                sc[1] = rem - cacc;
            }
        }
        __syncthreads();
        prefix = sc[0]; need = sc[1];
        __syncthreads();
    }

    if (tid == 0) { cHi = 0; cEq = 0; }
    __syncthreads();
    int base = q * KK;
    int takeEq = (int)need;
    int nAbove = KK - takeEq;
    for (int j = tid; j < NPTS; j += 128) {
        unsigned k = key[j];
        if (k > prefix) {
            int p = atomicAdd(&cHi, 1);
            d_idx[base + p] = j;
        } else if (k == prefix) {
            int p = atomicAdd(&cEq, 1);
            if (p < takeEq) d_idx[base + nAbove + p] = j;
        }
    }
}

// ---------------- edge conv: gather(P,C)->lrelu->conv(W)->max -----------------
// one point per 64-thread block; thread owns ONE channel.
// conv loop: 2 neighbors per iteration -> 4 independent fma2 chains (ILP),
// weights premultiplied by s at load so per-k epilogue is +b only.
__global__ void __launch_bounds__(64) edge_conv_kernel(
    const float* __restrict__ W, const float* __restrict__ sv, const float* __restrict__ bv,
    int outOff) {
    int q = blockIdx.x;
    int c = threadIdx.x;
    int rowbase = q & ~4095;           // batch base: d_idx holds within-batch indices
    __shared__ __align__(16) float h[KK][64];
    __shared__ int sj[KK];
    if (c < KK) sj[c] = d_idx[q * KK + c];
    __syncthreads();
    float Cq = d_cst[q * 64 + c];
    #pragma unroll 4
    for (int k = 0; k < KK; k++)
        h[k][c] = lrelu(d_P[(rowbase + sj[k]) * 64 + c] + Cq);
    float s = sv[c], bb = bv[c];
    ull s2 = pack2(s, s);
    ulonglong2 w[16];
    #pragma unroll
    for (int i = 0; i < 16; i++) {
        ulonglong2 wr = ((const ulonglong2*)(W + c * 64))[i];
        w[i].x = mul2(wr.x, s2);
        w[i].y = mul2(wr.y, s2);
    }
    __syncthreads();
    float m = -3.4e38f;
    for (int k = 0; k < KK; k += 2) {
        ull a0 = 0ULL, a1 = 0ULL, b0 = 0ULL, b1 = 0ULL;
        const ulonglong2* hp0 = (const ulonglong2*)&h[k][0];
        const ulonglong2* hp1 = (const ulonglong2*)&h[k + 1][0];
        #pragma unroll
        for (int i = 0; i < 16; i++) {
            ulonglong2 h20 = hp0[i];
            ulonglong2 h21 = hp1[i];
            a0 = fma2(w[i].x, h20.x, a0);
            a1 = fma2(w[i].y, h20.y, a1);
            b0 = fma2(w[i].x, h21.x, b0);
            b1 = fma2(w[i].y, h21.y, b1);
        }
        m = fmaxf(m, lrelu((red2(a0) + red2(a1)) + bb));
        m = fmaxf(m, lrelu((red2(b0) + red2(b1)) + bb));
    }
    d_feats[q * 192 + outOff + c] = m;
}

// ---------------- stage 3: pure gather-max (no conv) --------------------------
__global__ void __launch_bounds__(256) gather_max_kernel() {
    int t = blockIdx.x * 256 + threadIdx.x;
    int q = t >> 6, c = t & 63;
    int rowbase = q & ~4095;           // batch base
    float Cq = d_cst[q * 64 + c];
    const int* ip = d_idx + q * KK;
    float m = -3.4e38f;
    #pragma unroll 8
    for (int k = 0; k < KK; k++)
        m = fmaxf(m, lrelu(d_P[(rowbase + ip[k]) * 64 + c] + Cq));
    d_feats[q * 192 + 128 + c] = m;
}

// ---------------- tiled GEMM: C[M,N] = A[M,K] @ B[N,K]^T ----------------------
// 128x64 block tile, 256 threads, 8x4 per-thread f32x2 micro-tile,
// double-buffered smem (global prefetch overlapped with compute).
// EPI: 0 plain, 1 scale/bias/lrelu, 2 +gterm+scale/bias/lrelu,
//      3 conv6 (col-max + atomicMax), 4 conv9 (bias, transposed store),
//      5 a*s+b (affine, no lrelu), 6 a*s (scale only)
template <int EPI>
__global__ void __launch_bounds__(256) gemm_k(
    const float* __restrict__ A, int lda,
    const float* __restrict__ B, int ldb, int nrows,
    int K, float* __restrict__ C, int ldc,
    const float* __restrict__ sv, const float* __restrict__ bv) {
    __shared__ __align__(16) float As[2][128][18];
    __shared__ __align__(16) float Bs[2][64][18];
    int tid = threadIdx.x;
    int tx = tid & 15, ty = tid >> 4;
    int mBase = blockIdx.y * 128, nBase = blockIdx.x * 64;
    int lrA = tid >> 1, lcA = (tid & 1) * 8;
    int lrB = tid >> 2, lcB = (tid & 3) * 4;
    const float* Ap = A + (mBase + lrA) * lda + lcA;
    const float* Bp = B + (nBase + lrB) * ldb + lcB;
    bool bval = (nBase + lrB) < nrows;

    // load tile 0
    float4 a0 = *(const float4*)(Ap);
    float4 a1 = *(const float4*)(Ap + 4);
    float4 bw = bval ? *(const float4*)(Bp) : make_float4(0.f, 0.f, 0.f, 0.f);
    *(float2*)&As[0][lrA][lcA]     = make_float2(a0.x, a0.y);
    *(float2*)&As[0][lrA][lcA + 2] = make_float2(a0.z, a0.w);
    *(float2*)&As[0][lrA][lcA + 4] = make_float2(a1.x, a1.y);
    *(float2*)&As[0][lrA][lcA + 6] = make_float2(a1.z, a1.w);
    *(float2*)&Bs[0][lrB][lcB]     = make_float2(bw.x, bw.y);
    *(float2*)&Bs[0][lrB][lcB + 2] = make_float2(bw.z, bw.w);
    __syncthreads();

    ull acc2[8][4] = {};
    int buf = 0;
    for (int kt = 16; kt <= K; kt += 16) {
        bool has_next = kt < K;
        if (has_next) {
            a0 = *(const float4*)(Ap + kt);
            a1 = *(const float4*)(Ap + kt + 4);
            bw = bval ? *(const float4*)(Bp + kt) : make_float4(0.f, 0.f, 0.f, 0.f);
        }
        #pragma unroll
        for (int kk = 0; kk < 8; kk++) {
            ull a2[8], b2[4];
            #pragma unroll
            for (int mi = 0; mi < 8; mi++) a2[mi] = *(const ull*)&As[buf][ty + mi * 16][kk * 2];
            #pragma unroll
            for (int ni = 0; ni < 4; ni++) b2[ni] = *(const ull*)&Bs[buf][tx + ni * 16][kk * 2];
            #pragma unroll
            for (int mi = 0; mi < 8; mi++)
                #pragma unroll
                for (int ni = 0; ni < 4; ni++)
                    acc2[mi][ni] = fma2(a2[mi], b2[ni], acc2[mi][ni]);
        }
        if (has_next) {
            int nb = buf ^ 1;
            *(float2*)&As[nb][lrA][lcA]     = make_float2(a0.x, a0.y);
            *(float2*)&As[nb][lrA][lcA + 2] = make_float2(a0.z, a0.w);
            *(float2*)&As[nb][lrA][lcA + 4] = make_float2(a1.x, a1.y);
            *(float2*)&As[nb][lrA][lcA + 6] = make_float2(a1.z, a1.w);
            *(float2*)&Bs[nb][lrB][lcB]     = make_float2(bw.x, bw.y);
            *(float2*)&Bs[nb][lrB][lcB + 2] = make_float2(bw.z, bw.w);
            __syncthreads();
            buf = nb;
        }
    }

    float acc[8][4];
    #pragma unroll
    for (int mi = 0; mi < 8; mi++)
        #pragma unroll
        for (int ni = 0; ni < 4; ni++) acc[mi][ni] = red2(acc2[mi][ni]);

    if (EPI == 3) {
        int bb = mBase >> 12;
        float cm[4];
        #pragma unroll
        for (int ni = 0; ni < 4; ni++) {
            int nn = nBase + tx + ni * 16;
            float s = sv[nn], bbv = bv[nn];
            float m = -3.4e38f;
            #pragma unroll
            for (int mi = 0; mi < 8; mi++)
                m = fmaxf(m, lrelu(acc[mi][ni] * s + bbv));
            cm[ni] = m;
        }
        float* stage = &As[0][0][0];   // 16*64 floats, plenty of room
        __syncthreads();
        #pragma unroll
        for (int ni = 0; ni < 4; ni++) stage[ty * 64 + tx + ni * 16] = cm[ni];
        __syncthreads();
        if (tid < 64) {
            float m = stage[tid];
            #pragma unroll
            for (int r = 1; r < 16; r++) m = fmaxf(m, stage[r * 64 + tid]);
            atomicMax(&d_gmax[bb * 1024 + nBase + tid], fkey(m));
        }
        return;
    }

    #pragma unroll
    for (int mi = 0; mi < 8; mi++) {
        int m = mBase + ty + mi * 16;
        #pragma unroll
        for (int ni = 0; ni < 4; ni++) {
            int n = nBase + tx + ni * 16;
            float a = acc[mi][ni];
            if (EPI == 0) {
                C[m * ldc + n] = a;
            } else if (EPI == 1) {
                C[m * ldc + n] = lrelu(a * sv[n] + bv[n]);
            } else if (EPI == 2) {
                int bb = m >> 12;
                C[m * ldc + n] = lrelu((a + d_gterm[bb * 512 + n]) * sv[n] + bv[n]);
            } else if (EPI == 5) {
                C[m * ldc + n] = a * sv[n] + bv[n];
            } else if (EPI == 6) {
                C[m * ldc + n] = a * sv[n];
            } else { // EPI == 4 : conv9, transposed output (B,63,N)
                if (n < 63) {
                    int bb = m >> 12; int nn = m & 4095;
                    C[(bb * 63 + n) * 4096 + nn] = a + bv[n];
                }
            }
        }
    }
}

// ---------------- gterm: g[b] @ W7[:, :1024]^T --------------------------------
__global__ void __launch_bounds__(256) gterm_kernel(const float* __restrict__ W7) {
    int b = blockIdx.x >> 3;
    int cg = blockIdx.x & 7;   // group of 64 couts
    __shared__ float gs[1024];
    __shared__ float warpsum[8];
    int tid = threadIdx.x;
    for (int i = tid; i < 1024; i += 256) gs[i] = fdecode(d_gmax[b * 1024 + i]);
    __syncthreads();
    for (int cl = 0; cl < 64; cl++) {
        int cOut = cg * 64 + cl;
        float4 wv = ((const float4*)(W7 + cOut * 1216))[tid];
        float4 g4 = *(const float4*)&gs[tid * 4];
        float p = wv.x * g4.x + wv.y * g4.y + wv.z * g4.z + wv.w * g4.w;
        #pragma unroll
        for (int o = 16; o > 0; o >>= 1) p += __shfl_down_sync(0xffffffffu, p, o);
        if ((tid & 31) == 0) warpsum[tid >> 5] = p;
        __syncthreads();
        if (tid == 0) {
            float s = 0;
            #pragma unroll
            for (int r = 0; r < 8; r++) s += warpsum[r];
            d_gterm[b * 512 + cOut] = s;
        }
        __syncthreads();
    }
}

// ---------------- host --------------------------------------------------------
extern "C" void kernel_launch(void* const* d_in, const int* in_sizes, int n_in,
                              void* d_out, int out_size) {
    const float* x  = (const float*)d_in[0];
    const float* W1 = (const float*)d_in[1];
    const float* s1 = (const float*)d_in[2];
    const float* b1 = (const float*)d_in[3];
    const float* W2 = (const float*)d_in[4];
    const float* s2 = (const float*)d_in[5];
    const float* b2 = (const float*)d_in[6];
    const float* W3 = (const float*)d_in[7];
    const float* s3 = (const float*)d_in[8];
    const float* b3 = (const float*)d_in[9];
    const float* W4 = (const float*)d_in[10];
    const float* s4 = (const float*)d_in[11];
    const float* b4 = (const float*)d_in[12];
    const float* W5 = (const float*)d_in[13];
    const float* s5 = (const float*)d_in[14];
    const float* b5 = (const float*)d_in[15];
    const float* W6 = (const float*)d_in[16];
    const float* s6 = (const float*)d_in[17];
    const float* b6 = (const float*)d_in[18];
    const float* W7 = (const float*)d_in[19];
    const float* s7 = (const float*)d_in[20];
    const float* b7 = (const float*)d_in[21];
    const float* W8 = (const float*)d_in[22];
    const float* s8 = (const float*)d_in[23];
    const float* b8 = (const float*)d_in[24];
    const float* W9 = (const float*)d_in[25];
    const float* b9 = (const float*)d_in[26];
    float* out = (float*)d_out;

    float *feats, *cst, *P, *h7, *h8, *wd3, *wd5;
    cudaGetSymbolAddress((void**)&feats, d_feats);
    cudaGetSymbolAddress((void**)&cst,   d_cst);
    cudaGetSymbolAddress((void**)&P,     d_P);
    cudaGetSymbolAddress((void**)&h7,    d_h7);
    cudaGetSymbolAddress((void**)&h8,    d_h8);
    cudaGetSymbolAddress((void**)&wd3,   d_wd3);
    cudaGetSymbolAddress((void**)&wd5,   d_wd5);

    knn_kernel<<<BN_TOT, 128>>>(x);                             // 0
    prep1_kernel<<<4096, 256>>>(x, W1, s1, b1);                 // 1
    prep_w_kernel<<<32, 256>>>(W3, W5);                         // 2
    // stage1: gather(P1,C1) -> conv2 -> max -> x1
    edge_conv_kernel<<<BN_TOT, 64>>>(W2, s2, b2, 0);            // 3  <- ncu captures this
    prep_g_kernel<<<16, 256>>>();
    // stage2 precompute: P = (x1 @ W3lo^T)*s3 ; C = (x1 @ wd3^T)*s3 + b3
    gemm_k<6><<<dim3(1, 128), 256>>>(feats, 192, W3, 128, 64, 64, P, 64, s3, nullptr);
    gemm_k<5><<<dim3(1, 128), 256>>>(feats, 192, wd3, 64, 64, 64, cst, 64, s3, b3);
    // stage2: gather -> conv4 -> max -> x2
    edge_conv_kernel<<<BN_TOT, 64>>>(W4, s4, b4, 64);
    // stage3 precompute: P = (x2 @ W5lo^T)*s5 ; C = (x2 @ wd5^T)*s5 + b5
    gemm_k<6><<<dim3(1, 128), 256>>>(feats + 64, 192, W5, 128, 64, 64, P, 64, s5, nullptr);
    gemm_k<5><<<dim3(1, 128), 256>>>(feats + 64, 192, wd5, 64, 64, 64, cst, 64, s5, b5);
    // stage3: pure gather-max -> x3
    gather_max_kernel<<<4096, 256>>>();
    // conv6 + global max over N (per batch, per channel)
    gemm_k<3><<<dim3(16, 128), 256>>>(feats, 192, W6, 192, 1024, 192, nullptr, 0, s6, b6);
    // gterm[b] = g[b] @ W7[:, :1024]^T
    gterm_kernel<<<32, 256>>>(W7);
    // conv7 on feature part only (K=192) + gterm in epilogue
    gemm_k<2><<<dim3(8, 128), 256>>>(feats, 192, W7 + 1024, 1216, 512, 192, h7, 512, s7, b7);
    // conv8
    gemm_k<1><<<dim3(4, 128), 256>>>(h7, 512, W8, 512, 256, 512, h8, 256, s8, b8);
    // conv9 -> transposed output (B, 63, N)
    gemm_k<4><<<dim3(1, 128), 256>>>(h8, 256, W9, 256, 63, 256, out, 0, nullptr, b9);
}

// round 14
// speedup vs baseline: 1.5926x; 1.5926x over previous
#include <cuda_runtime.h>

#define BN_TOT 16384   // B*N = 4*4096
#define NPTS   4096
#define KK     40

typedef unsigned long long ull;

// ---------------- scratch (device globals; no allocation allowed) -------------
__device__ int      d_idx[BN_TOT * KK];
__device__ float    d_feats[BN_TOT * 192];   // [x1 | x2 | x3]
__device__ float    d_P[BN_TOT * 64];        // per-stage neighbor term (scaled)
__device__ float    d_cst[BN_TOT * 64];      // per-stage center term (affine folded)
__device__ float    d_h7[BN_TOT * 512];
__device__ float    d_h8[BN_TOT * 256];
__device__ unsigned d_gmax[4 * 1024];        // per-batch conv6 max (order-preserving uint)
__device__ float    d_wd3[64 * 64];          // W3[:,64:128]-W3[:,0:64]
__device__ float    d_wd5[64 * 64];
__device__ float    d_gterm[4 * 512];        // g @ W7[:, :1024]^T  per batch

__device__ __forceinline__ unsigned fkey(float f) {
    unsigned u = __float_as_uint(f);
    return (u & 0x80000000u) ? ~u : (u | 0x80000000u);
}
__device__ __forceinline__ float fdecode(unsigned k) {
    return (k & 0x80000000u) ? __uint_as_float(k ^ 0x80000000u) : __uint_as_float(~k);
}
__device__ __forceinline__ float lrelu(float v) { return v >= 0.f ? v : 0.2f * v; }

// packed fp32x2 FMA (Blackwell)
__device__ __forceinline__ ull fma2(ull a, ull b, ull c) {
    ull d;
    asm("fma.rn.f32x2 %0, %1, %2, %3;" : "=l"(d) : "l"(a), "l"(b), "l"(c));
    return d;
}
__device__ __forceinline__ ull mul2(ull a, ull b) {
    ull d;
    asm("mul.rn.f32x2 %0, %1, %2;" : "=l"(d) : "l"(a), "l"(b));
    return d;
}
__device__ __forceinline__ float red2(ull a) {
    float x, y;
    asm("mov.b64 {%0, %1}, %2;" : "=f"(x), "=f"(y) : "l"(a));
    return x + y;
}
__device__ __forceinline__ ull pack2(float x, float y) {
    ull d;
    asm("mov.b64 %0, {%1, %2};" : "=l"(d) : "f"(x), "f"(y));
    return d;
}

// ---------------- prep kernels ------------------------------------------------
__global__ void prep_w_kernel(const float* __restrict__ W3, const float* __restrict__ W5) {
    int t = blockIdx.x * blockDim.x + threadIdx.x;
    if (t < 4096) {
        int c = t >> 6, i = t & 63;
        d_wd3[t] = W3[c * 128 + 64 + i] - W3[c * 128 + i];
    } else if (t < 8192) {
        int u = t - 4096; int c = u >> 6, i = u & 63;
        d_wd5[u] = W5[c * 128 + 64 + i] - W5[c * 128 + i];
    }
}
__global__ void prep_g_kernel() {
    int t = blockIdx.x * blockDim.x + threadIdx.x;
    if (t < 4096) d_gmax[t] = 0u;
}

// stage1 P/C: P[q,c] = (W1lo[c]·xyz_q)*s1[c], C[q,c] = ((W1hi-W1lo)[c]·xyz_q)*s1[c]+b1[c]
__global__ void __launch_bounds__(256) prep1_kernel(
    const float* __restrict__ x, const float* __restrict__ W1,
    const float* __restrict__ s1, const float* __restrict__ b1) {
    int t = blockIdx.x * 256 + threadIdx.x;
    int q = t >> 6, c = t & 63;
    int b = q >> 12, n = q & 4095;
    const float* xb = x + b * 3 * NPTS;
    float cx = xb[n], cy = xb[NPTS + n], cz = xb[2 * NPTS + n];
    float w0 = W1[c * 6 + 0], w1 = W1[c * 6 + 1], w2 = W1[c * 6 + 2];
    float w3 = W1[c * 6 + 3], w4 = W1[c * 6 + 4], w5 = W1[c * 6 + 5];
    float s = s1[c];
    d_P[q * 64 + c]   = (w0 * cx + w1 * cy + w2 * cz) * s;
    d_cst[q * 64 + c] = ((w3 - w0) * cx + (w4 - w1) * cy + (w5 - w2) * cz) * s + b1[c];
}

// ---------------- KNN: radix top-40; match-aggregated atomics in pass 0 -------
__global__ void __launch_bounds__(128) knn_kernel(const float* __restrict__ x) {
    const int q = blockIdx.x;
    const int b = q >> 12, n = q & 4095;
    const int tid = threadIdx.x;
    __shared__ unsigned key[NPTS];
    __shared__ unsigned hist[256];
    __shared__ unsigned sc[2];
    __shared__ int cHi, cEq;

    const float* xb = x + b * 3 * NPTS;
    float cx = xb[n], cy = xb[NPTS + n], cz = xb[2 * NPTS + n];
    float xxi = cx * cx + cy * cy + cz * cz;

    for (int j = tid; j < NPTS; j += 128) {
        float px = xb[j], py = xb[NPTS + j], pz = xb[2 * NPTS + j];
        float dot = cx * px + cy * py + cz * pz;
        float xxj = px * px + py * py + pz * pz;
        float d = (2.f * dot - xxi) - xxj;   // = -||xi-xj||^2, larger = nearer
        key[j] = fkey(d);
    }

    unsigned prefix = 0, need = KK;
    for (int pass = 0; pass < 4; ++pass) {
        int shift = 24 - 8 * pass;
        unsigned himask = (pass == 0) ? 0u : (0xFFFFFFFFu << (shift + 8));
        for (int i2 = tid; i2 < 256; i2 += 128) hist[i2] = 0u;
        __syncthreads();
        if (pass == 0) {
            for (int j = tid; j < NPTS; j += 128) {
                int bucket = (int)(key[j] >> shift);
                unsigned mm = __match_any_sync(0xffffffffu, bucket);
                if ((tid & 31) == (__ffs(mm) - 1))
                    atomicAdd(&hist[bucket], (unsigned)__popc(mm));
            }
        } else {
            for (int j = tid; j < NPTS; j += 128) {
                unsigned k = key[j];
                if ((k & himask) == (prefix & himask))
                    atomicAdd(&hist[(k >> shift) & 255], 1u);
            }
        }
        __syncthreads();
        if (tid < 32) {
            unsigned part[8]; unsigned s = 0;
            #pragma unroll
            for (int r = 0; r < 8; r++) { part[r] = hist[255 - tid * 8 - r]; s += part[r]; }
            unsigned inc = s;
            #pragma unroll
            for (int o = 1; o < 32; o <<= 1) {
                unsigned v = __shfl_up_sync(0xffffffffu, inc, o);
                if (tid >= o) inc += v;
            }
            unsigned excl = inc - s;
            unsigned ball = __ballot_sync(0xffffffffu, (excl < need) && (need <= inc));
            int lane = __ffs(ball) - 1;
            if (tid == lane) {
                unsigned rem = need - excl, cacc = 0; int r = 0;
                for (; r < 8; r++) { if (cacc + part[r] >= rem) break; cacc += part[r]; }
                unsigned v = 255u - (unsigned)(tid * 8) - (unsigned)r;
                sc[0] = prefix | (v << shift);
                sc[1] = rem - cacc;
            }
        }
        __syncthreads();
        prefix = sc[0]; need = sc[1];
        __syncthreads();
    }

    if (tid == 0) { cHi = 0; cEq = 0; }
    __syncthreads();
    int base = q * KK;
    int takeEq = (int)need;
    int nAbove = KK - takeEq;
    for (int j = tid; j < NPTS; j += 128) {
        unsigned k = key[j];
        if (k > prefix) {
            int p = atomicAdd(&cHi, 1);
            d_idx[base + p] = j;
        } else if (k == prefix) {
            int p = atomicAdd(&cEq, 1);
            if (p < takeEq) d_idx[base + nAbove + p] = j;
        }
    }
}

// ---------------- edge conv: gather(P,C)->lrelu->conv(W)->max -----------------
// one point per 64-thread block; thread owns ONE channel.
// R10 structure (1 neighbor/iter) + 4 accumulator chains (latency slack 2x),
// weights premultiplied by s at load.
__global__ void __launch_bounds__(64) edge_conv_kernel(
    const float* __restrict__ W, const float* __restrict__ sv, const float* __restrict__ bv,
    int outOff) {
    int q = blockIdx.x;
    int c = threadIdx.x;
    int rowbase = q & ~4095;           // batch base: d_idx holds within-batch indices
    __shared__ __align__(16) float h[KK][64];
    __shared__ int sj[KK];
    if (c < KK) sj[c] = d_idx[q * KK + c];
    __syncthreads();
    float Cq = d_cst[q * 64 + c];
    #pragma unroll 4
    for (int k = 0; k < KK; k++)
        h[k][c] = lrelu(d_P[(rowbase + sj[k]) * 64 + c] + Cq);
    float s = sv[c], bb = bv[c];
    ull s2 = pack2(s, s);
    ulonglong2 w[16];
    #pragma unroll
    for (int i = 0; i < 16; i++) {
        ulonglong2 wr = ((const ulonglong2*)(W + c * 64))[i];
        w[i].x = mul2(wr.x, s2);
        w[i].y = mul2(wr.y, s2);
    }
    __syncthreads();
    float m = -3.4e38f;
    for (int k = 0; k < KK; k++) {
        ull a0 = 0ULL, a1 = 0ULL, a2 = 0ULL, a3 = 0ULL;
        const ulonglong2* hp = (const ulonglong2*)&h[k][0];
        #pragma unroll
        for (int i = 0; i < 8; i++) {
            ulonglong2 hA = hp[i];
            ulonglong2 hB = hp[i + 8];
            a0 = fma2(w[i].x, hA.x, a0);
            a1 = fma2(w[i].y, hA.y, a1);
            a2 = fma2(w[i + 8].x, hB.x, a2);
            a3 = fma2(w[i + 8].y, hB.y, a3);
        }
        m = fmaxf(m, lrelu((red2(a0) + red2(a1)) + (red2(a2) + red2(a3)) + bb));
    }
    d_feats[q * 192 + outOff + c] = m;
}

// ---------------- stage 3: pure gather-max (no conv) --------------------------
__global__ void __launch_bounds__(256) gather_max_kernel() {
    int t = blockIdx.x * 256 + threadIdx.x;
    int q = t >> 6, c = t & 63;
    int rowbase = q & ~4095;           // batch base
    float Cq = d_cst[q * 64 + c];
    const int* ip = d_idx + q * KK;
    float m = -3.4e38f;
    #pragma unroll 8
    for (int k = 0; k < KK; k++)
        m = fmaxf(m, lrelu(d_P[(rowbase + ip[k]) * 64 + c] + Cq));
    d_feats[q * 192 + 128 + c] = m;
}

// ---------------- tiled GEMM: C[M,N] = A[M,K] @ B[N,K]^T ----------------------
// 128x64 block tile, 256 threads, 8x4 per-thread f32x2 micro-tile,
// double-buffered smem (global prefetch overlapped with compute).
// EPI: 0 plain, 1 scale/bias/lrelu, 2 +gterm+scale/bias/lrelu,
//      3 conv6 (col-max + atomicMax), 4 conv9 (bias, transposed store),
//      5 a*s+b (affine, no lrelu), 6 a*s (scale only)
template <int EPI>
__global__ void __launch_bounds__(256) gemm_k(
    const float* __restrict__ A, int lda,
    const float* __restrict__ B, int ldb, int nrows,
    int K, float* __restrict__ C, int ldc,
    const float* __restrict__ sv, const float* __restrict__ bv) {
    __shared__ __align__(16) float As[2][128][18];
    __shared__ __align__(16) float Bs[2][64][18];
    int tid = threadIdx.x;
    int tx = tid & 15, ty = tid >> 4;
    int mBase = blockIdx.y * 128, nBase = blockIdx.x * 64;
    int lrA = tid >> 1, lcA = (tid & 1) * 8;
    int lrB = tid >> 2, lcB = (tid & 3) * 4;
    const float* Ap = A + (mBase + lrA) * lda + lcA;
    const float* Bp = B + (nBase + lrB) * ldb + lcB;
    bool bval = (nBase + lrB) < nrows;

    // load tile 0
    float4 a0 = *(const float4*)(Ap);
    float4 a1 = *(const float4*)(Ap + 4);
    float4 bw = bval ? *(const float4*)(Bp) : make_float4(0.f, 0.f, 0.f, 0.f);
    *(float2*)&As[0][lrA][lcA]     = make_float2(a0.x, a0.y);
    *(float2*)&As[0][lrA][lcA + 2] = make_float2(a0.z, a0.w);
    *(float2*)&As[0][lrA][lcA + 4] = make_float2(a1.x, a1.y);
    *(float2*)&As[0][lrA][lcA + 6] = make_float2(a1.z, a1.w);
    *(float2*)&Bs[0][lrB][lcB]     = make_float2(bw.x, bw.y);
    *(float2*)&Bs[0][lrB][lcB + 2] = make_float2(bw.z, bw.w);
    __syncthreads();

    ull acc2[8][4] = {};
    int buf = 0;
    for (int kt = 16; kt <= K; kt += 16) {
        bool has_next = kt < K;
        if (has_next) {
            a0 = *(const float4*)(Ap + kt);
            a1 = *(const float4*)(Ap + kt + 4);
            bw = bval ? *(const float4*)(Bp + kt) : make_float4(0.f, 0.f, 0.f, 0.f);
        }
        #pragma unroll
        for (int kk = 0; kk < 8; kk++) {
            ull a2[8], b2[4];
            #pragma unroll
            for (int mi = 0; mi < 8; mi++) a2[mi] = *(const ull*)&As[buf][ty + mi * 16][kk * 2];
            #pragma unroll
            for (int ni = 0; ni < 4; ni++) b2[ni] = *(const ull*)&Bs[buf][tx + ni * 16][kk * 2];
            #pragma unroll
            for (int mi = 0; mi < 8; mi++)
                #pragma unroll
                for (int ni = 0; ni < 4; ni++)
                    acc2[mi][ni] = fma2(a2[mi], b2[ni], acc2[mi][ni]);
        }
        if (has_next) {
            int nb = buf ^ 1;
            *(float2*)&As[nb][lrA][lcA]     = make_float2(a0.x, a0.y);
            *(float2*)&As[nb][lrA][lcA + 2] = make_float2(a0.z, a0.w);
            *(float2*)&As[nb][lrA][lcA + 4] = make_float2(a1.x, a1.y);
            *(float2*)&As[nb][lrA][lcA + 6] = make_float2(a1.z, a1.w);
            *(float2*)&Bs[nb][lrB][lcB]     = make_float2(bw.x, bw.y);
            *(float2*)&Bs[nb][lrB][lcB + 2] = make_float2(bw.z, bw.w);
            __syncthreads();
            buf = nb;
        }
    }

    float acc[8][4];
    #pragma unroll
    for (int mi = 0; mi < 8; mi++)
        #pragma unroll
        for (int ni = 0; ni < 4; ni++) acc[mi][ni] = red2(acc2[mi][ni]);

    if (EPI == 3) {
        int bb = mBase >> 12;
        float cm[4];
        #pragma unroll
        for (int ni = 0; ni < 4; ni++) {
            int nn = nBase + tx + ni * 16;
            float s = sv[nn], bbv = bv[nn];
            float m = -3.4e38f;
            #pragma unroll
            for (int mi = 0; mi < 8; mi++)
                m = fmaxf(m, lrelu(acc[mi][ni] * s + bbv));
            cm[ni] = m;
        }
        float* stage = &As[0][0][0];   // 16*64 floats, plenty of room
        __syncthreads();
        #pragma unroll
        for (int ni = 0; ni < 4; ni++) stage[ty * 64 + tx + ni * 16] = cm[ni];
        __syncthreads();
        if (tid < 64) {
            float m = stage[tid];
            #pragma unroll
            for (int r = 1; r < 16; r++) m = fmaxf(m, stage[r * 64 + tid]);
            atomicMax(&d_gmax[bb * 1024 + nBase + tid], fkey(m));
        }
        return;
    }

    #pragma unroll
    for (int mi = 0; mi < 8; mi++) {
        int m = mBase + ty + mi * 16;
        #pragma unroll
        for (int ni = 0; ni < 4; ni++) {
            int n = nBase + tx + ni * 16;
            float a = acc[mi][ni];
            if (EPI == 0) {
                C[m * ldc + n] = a;
            } else if (EPI == 1) {
                C[m * ldc + n] = lrelu(a * sv[n] + bv[n]);
            } else if (EPI == 2) {
                int bb = m >> 12;
                C[m * ldc + n] = lrelu((a + d_gterm[bb * 512 + n]) * sv[n] + bv[n]);
            } else if (EPI == 5) {
                C[m * ldc + n] = a * sv[n] + bv[n];
            } else if (EPI == 6) {
                C[m * ldc + n] = a * sv[n];
            } else { // EPI == 4 : conv9, transposed output (B,63,N)
                if (n < 63) {
                    int bb = m >> 12; int nn = m & 4095;
                    C[(bb * 63 + n) * 4096 + nn] = a + bv[n];
                }
            }
        }
    }
}

// ---------------- gterm: g[b] @ W7[:, :1024]^T --------------------------------
__global__ void __launch_bounds__(256) gterm_kernel(const float* __restrict__ W7) {
    int b = blockIdx.x >> 3;
    int cg = blockIdx.x & 7;   // group of 64 couts
    __shared__ float gs[1024];
    __shared__ float warpsum[8];
    int tid = threadIdx.x;
    for (int i = tid; i < 1024; i += 256) gs[i] = fdecode(d_gmax[b * 1024 + i]);
    __syncthreads();
    for (int cl = 0; cl < 64; cl++) {
        int cOut = cg * 64 + cl;
        float4 wv = ((const float4*)(W7 + cOut * 1216))[tid];
        float4 g4 = *(const float4*)&gs[tid * 4];
        float p = wv.x * g4.x + wv.y * g4.y + wv.z * g4.z + wv.w * g4.w;
        #pragma unroll
        for (int o = 16; o > 0; o >>= 1) p += __shfl_down_sync(0xffffffffu, p, o);
        if ((tid & 31) == 0) warpsum[tid >> 5] = p;
        __syncthreads();
        if (tid == 0) {
            float s = 0;
            #pragma unroll
            for (int r = 0; r < 8; r++) s += warpsum[r];
            d_gterm[b * 512 + cOut] = s;
        }
        __syncthreads();
    }
}

// ---------------- host --------------------------------------------------------
extern "C" void kernel_launch(void* const* d_in, const int* in_sizes, int n_in,
                              void* d_out, int out_size) {
    const float* x  = (const float*)d_in[0];
    const float* W1 = (const float*)d_in[1];
    const float* s1 = (const float*)d_in[2];
    const float* b1 = (const float*)d_in[3];
    const float* W2 = (const float*)d_in[4];
    const float* s2 = (const float*)d_in[5];
    const float* b2 = (const float*)d_in[6];
    const float* W3 = (const float*)d_in[7];
    const float* s3 = (const float*)d_in[8];
    const float* b3 = (const float*)d_in[9];
    const float* W4 = (const float*)d_in[10];
    const float* s4 = (const float*)d_in[11];
    const float* b4 = (const float*)d_in[12];
    const float* W5 = (const float*)d_in[13];
    const float* s5 = (const float*)d_in[14];
    const float* b5 = (const float*)d_in[15];
    const float* W6 = (const float*)d_in[16];
    const float* s6 = (const float*)d_in[17];
    const float* b6 = (const float*)d_in[18];
    const float* W7 = (const float*)d_in[19];
    const float* s7 = (const float*)d_in[20];
    const float* b7 = (const float*)d_in[21];
    const float* W8 = (const float*)d_in[22];
    const float* s8 = (const float*)d_in[23];
    const float* b8 = (const float*)d_in[24];
    const float* W9 = (const float*)d_in[25];
    const float* b9 = (const float*)d_in[26];
    float* out = (float*)d_out;

    float *feats, *cst, *P, *h7, *h8, *wd3, *wd5;
    cudaGetSymbolAddress((void**)&feats, d_feats);
    cudaGetSymbolAddress((void**)&cst,   d_cst);
    cudaGetSymbolAddress((void**)&P,     d_P);
    cudaGetSymbolAddress((void**)&h7,    d_h7);
    cudaGetSymbolAddress((void**)&h8,    d_h8);
    cudaGetSymbolAddress((void**)&wd3,   d_wd3);
    cudaGetSymbolAddress((void**)&wd5,   d_wd5);

    knn_kernel<<<BN_TOT, 128>>>(x);                             // 0
    prep1_kernel<<<4096, 256>>>(x, W1, s1, b1);                 // 1
    prep_w_kernel<<<32, 256>>>(W3, W5);                         // 2
    // stage1: gather(P1,C1) -> conv2 -> max -> x1
    edge_conv_kernel<<<BN_TOT, 64>>>(W2, s2, b2, 0);            // 3  <- ncu captures this
    prep_g_kernel<<<16, 256>>>();
    // stage2 precompute: P = (x1 @ W3lo^T)*s3 ; C = (x1 @ wd3^T)*s3 + b3
    gemm_k<6><<<dim3(1, 128), 256>>>(feats, 192, W3, 128, 64, 64, P, 64, s3, nullptr);
    gemm_k<5><<<dim3(1, 128), 256>>>(feats, 192, wd3, 64, 64, 64, cst, 64, s3, b3);
    // stage2: gather -> conv4 -> max -> x2
    edge_conv_kernel<<<BN_TOT, 64>>>(W4, s4, b4, 64);
    // stage3 precompute: P = (x2 @ W5lo^T)*s5 ; C = (x2 @ wd5^T)*s5 + b5
    gemm_k<6><<<dim3(1, 128), 256>>>(feats + 64, 192, W5, 128, 64, 64, P, 64, s5, nullptr);
    gemm_k<5><<<dim3(1, 128), 256>>>(feats + 64, 192, wd5, 64, 64, 64, cst, 64, s5, b5);
    // stage3: pure gather-max -> x3
    gather_max_kernel<<<4096, 256>>>();
    // conv6 + global max over N (per batch, per channel)
    gemm_k<3><<<dim3(16, 128), 256>>>(feats, 192, W6, 192, 1024, 192, nullptr, 0, s6, b6);
    // gterm[b] = g[b] @ W7[:, :1024]^T
    gterm_kernel<<<32, 256>>>(W7);
    // conv7 on feature part only (K=192) + gterm in epilogue
    gemm_k<2><<<dim3(8, 128), 256>>>(feats, 192, W7 + 1024, 1216, 512, 192, h7, 512, s7, b7);
    // conv8
    gemm_k<1><<<dim3(4, 128), 256>>>(h7, 512, W8, 512, 256, 512, h8, 256, s8, b8);
    // conv9 -> transposed output (B, 63, N)
    gemm_k<4><<<dim3(1, 128), 256>>>(h8, 256, W9, 256, 63, 256, out, 0, nullptr, b9);
}

// round 15
// speedup vs baseline: 1.7267x; 1.0842x over previous
#include <cuda_runtime.h>

#define BN_TOT 16384   // B*N = 4*4096
#define NPTS   4096
#define KK     40

typedef unsigned long long ull;

// ---------------- scratch (device globals; no allocation allowed) -------------
__device__ int      d_idx[BN_TOT * KK];
__device__ float    d_feats[BN_TOT * 192];   // [x1 | x2 | x3]
__device__ float    d_P[BN_TOT * 64];        // per-stage neighbor term (scaled)
__device__ float    d_cst[BN_TOT * 64];      // per-stage center term (affine folded)
__device__ float    d_h7[BN_TOT * 512];
__device__ float    d_h8[BN_TOT * 256];
__device__ unsigned d_gmax[4 * 1024];        // per-batch conv6 max (order-preserving uint)
__device__ float    d_wd3[64 * 64];          // W3[:,64:128]-W3[:,0:64]
__device__ float    d_wd5[64 * 64];
__device__ float    d_gterm[4 * 512];        // g @ W7[:, :1024]^T  per batch

__device__ __forceinline__ unsigned fkey(float f) {
    unsigned u = __float_as_uint(f);
    return (u & 0x80000000u) ? ~u : (u | 0x80000000u);
}
__device__ __forceinline__ float fdecode(unsigned k) {
    return (k & 0x80000000u) ? __uint_as_float(k ^ 0x80000000u) : __uint_as_float(~k);
}
__device__ __forceinline__ float lrelu(float v) { return v >= 0.f ? v : 0.2f * v; }

// packed fp32x2 FMA (Blackwell)
__device__ __forceinline__ ull fma2(ull a, ull b, ull c) {
    ull d;
    asm("fma.rn.f32x2 %0, %1, %2, %3;" : "=l"(d) : "l"(a), "l"(b), "l"(c));
    return d;
}
__device__ __forceinline__ ull mul2(ull a, ull b) {
    ull d;
    asm("mul.rn.f32x2 %0, %1, %2;" : "=l"(d) : "l"(a), "l"(b));
    return d;
}
__device__ __forceinline__ float red2(ull a) {
    float x, y;
    asm("mov.b64 {%0, %1}, %2;" : "=f"(x), "=f"(y) : "l"(a));
    return x + y;
}
__device__ __forceinline__ ull pack2(float x, float y) {
    ull d;
    asm("mov.b64 %0, {%1, %2};" : "=l"(d) : "f"(x), "f"(y));
    return d;
}

// ---------------- prep kernels ------------------------------------------------
__global__ void prep_w_kernel(const float* __restrict__ W3, const float* __restrict__ W5) {
    int t = blockIdx.x * blockDim.x + threadIdx.x;
    if (t < 4096) {
        int c = t >> 6, i = t & 63;
        d_wd3[t] = W3[c * 128 + 64 + i] - W3[c * 128 + i];
    } else if (t < 8192) {
        int u = t - 4096; int c = u >> 6, i = u & 63;
        d_wd5[u] = W5[c * 128 + 64 + i] - W5[c * 128 + i];
    }
}
__global__ void prep_g_kernel() {
    int t = blockIdx.x * blockDim.x + threadIdx.x;
    if (t < 4096) d_gmax[t] = 0u;
}

// stage1 P/C: P[q,c] = (W1lo[c]·xyz_q)*s1[c], C[q,c] = ((W1hi-W1lo)[c]·xyz_q)*s1[c]+b1[c]
__global__ void __launch_bounds__(256) prep1_kernel(
    const float* __restrict__ x, const float* __restrict__ W1,
    const float* __restrict__ s1, const float* __restrict__ b1) {
    int t = blockIdx.x * 256 + threadIdx.x;
    int q = t >> 6, c = t & 63;
    int b = q >> 12, n = q & 4095;
    const float* xb = x + b * 3 * NPTS;
    float cx = xb[n], cy = xb[NPTS + n], cz = xb[2 * NPTS + n];
    float w0 = W1[c * 6 + 0], w1 = W1[c * 6 + 1], w2 = W1[c * 6 + 2];
    float w3 = W1[c * 6 + 3], w4 = W1[c * 6 + 4], w5 = W1[c * 6 + 5];
    float s = s1[c];
    d_P[q * 64 + c]   = (w0 * cx + w1 * cy + w2 * cz) * s;
    d_cst[q * 64 + c] = ((w3 - w0) * cx + (w4 - w1) * cy + (w5 - w2) * cz) * s + b1[c];
}

// ---------------- KNN: radix top-40; match-aggregated atomics in pass 0 -------
__global__ void __launch_bounds__(128) knn_kernel(const float* __restrict__ x) {
    const int q = blockIdx.x;
    const int b = q >> 12, n = q & 4095;
    const int tid = threadIdx.x;
    __shared__ unsigned key[NPTS];
    __shared__ unsigned hist[256];
    __shared__ unsigned sc[2];
    __shared__ int cHi, cEq;

    const float* xb = x + b * 3 * NPTS;
    float cx = xb[n], cy = xb[NPTS + n], cz = xb[2 * NPTS + n];
    float xxi = cx * cx + cy * cy + cz * cz;

    for (int j = tid; j < NPTS; j += 128) {
        float px = xb[j], py = xb[NPTS + j], pz = xb[2 * NPTS + j];
        float dot = cx * px + cy * py + cz * pz;
        float xxj = px * px + py * py + pz * pz;
        float d = (2.f * dot - xxi) - xxj;   // = -||xi-xj||^2, larger = nearer
        key[j] = fkey(d);
    }

    unsigned prefix = 0, need = KK;
    for (int pass = 0; pass < 4; ++pass) {
        int shift = 24 - 8 * pass;
        unsigned himask = (pass == 0) ? 0u : (0xFFFFFFFFu << (shift + 8));
        for (int i2 = tid; i2 < 256; i2 += 128) hist[i2] = 0u;
        __syncthreads();
        if (pass == 0) {
            for (int j = tid; j < NPTS; j += 128) {
                int bucket = (int)(key[j] >> shift);
                unsigned mm = __match_any_sync(0xffffffffu, bucket);
                if ((tid & 31) == (__ffs(mm) - 1))
                    atomicAdd(&hist[bucket], (unsigned)__popc(mm));
            }
        } else {
            for (int j = tid; j < NPTS; j += 128) {
                unsigned k = key[j];
                if ((k & himask) == (prefix & himask))
                    atomicAdd(&hist[(k >> shift) & 255], 1u);
            }
        }
        __syncthreads();
        if (tid < 32) {
            unsigned part[8]; unsigned s = 0;
            #pragma unroll
            for (int r = 0; r < 8; r++) { part[r] = hist[255 - tid * 8 - r]; s += part[r]; }
            unsigned inc = s;
            #pragma unroll
            for (int o = 1; o < 32; o <<= 1) {
                unsigned v = __shfl_up_sync(0xffffffffu, inc, o);
                if (tid >= o) inc += v;
            }
            unsigned excl = inc - s;
            unsigned ball = __ballot_sync(0xffffffffu, (excl < need) && (need <= inc));
            int lane = __ffs(ball) - 1;
            if (tid == lane) {
                unsigned rem = need - excl, cacc = 0; int r = 0;
                for (; r < 8; r++) { if (cacc + part[r] >= rem) break; cacc += part[r]; }
                unsigned v = 255u - (unsigned)(tid * 8) - (unsigned)r;
                sc[0] = prefix | (v << shift);
                sc[1] = rem - cacc;
            }
        }
        __syncthreads();
        prefix = sc[0]; need = sc[1];
        __syncthreads();
    }

    if (tid == 0) { cHi = 0; cEq = 0; }
    __syncthreads();
    int base = q * KK;
    int takeEq = (int)need;
    int nAbove = KK - takeEq;
    for (int j = tid; j < NPTS; j += 128) {
        unsigned k = key[j];
        if (k > prefix) {
            int p = atomicAdd(&cHi, 1);
            d_idx[base + p] = j;
        } else if (k == prefix) {
            int p = atomicAdd(&cEq, 1);
            if (p < takeEq) d_idx[base + nAbove + p] = j;
        }
    }
}

// ---------------- edge conv: gather(P,C)->lrelu->conv(W)->max -----------------
// ONE WARP per point (2 points / 64-thread block); lane owns channels (c, c+32).
// Each broadcast h-row read feeds 64 fma2 (2x reuse) -> crossbar:fma = 2:1.
// Weights premultiplied by s; warp-private smem, no block syncs in main loop.
__global__ void __launch_bounds__(64) edge_conv_kernel(
    const float* __restrict__ W, const float* __restrict__ sv, const float* __restrict__ bv,
    int outOff) {
    int warp = threadIdx.x >> 5, lane = threadIdx.x & 31;
    int q = blockIdx.x * 2 + warp;
    int c0 = lane, c1 = lane + 32;
    int rowbase = q & ~4095;           // batch base: d_idx holds within-batch indices
    __shared__ __align__(16) float h[2][KK][64];
    __shared__ int sj[2][KK];
    for (int k = lane; k < KK; k += 32) sj[warp][k] = d_idx[q * KK + k];
    __syncwarp();
    float C0 = d_cst[q * 64 + c0];
    float C1 = d_cst[q * 64 + c1];
    #pragma unroll 4
    for (int k = 0; k < KK; k++) {
        const float* src = d_P + (rowbase + sj[warp][k]) * 64;
        h[warp][k][c0] = lrelu(src[c0] + C0);
        h[warp][k][c1] = lrelu(src[c1] + C1);
    }
    float sA = sv[c0], bbA = bv[c0];
    float sB = sv[c1], bbB = bv[c1];
    ull sA2 = pack2(sA, sA), sB2 = pack2(sB, sB);
    ulonglong2 wA[16], wB[16];
    #pragma unroll
    for (int i = 0; i < 16; i++) {
        ulonglong2 wr = ((const ulonglong2*)(W + c0 * 64))[i];
        wA[i].x = mul2(wr.x, sA2);
        wA[i].y = mul2(wr.y, sA2);
    }
    #pragma unroll
    for (int i = 0; i < 16; i++) {
        ulonglong2 wr = ((const ulonglong2*)(W + c1 * 64))[i];
        wB[i].x = mul2(wr.x, sB2);
        wB[i].y = mul2(wr.y, sB2);
    }
    __syncwarp();
    float m0 = -3.4e38f, m1 = -3.4e38f;
    for (int k = 0; k < KK; k++) {
        ull aA0 = 0ULL, aA1 = 0ULL, aB0 = 0ULL, aB1 = 0ULL;
        const ulonglong2* hp = (const ulonglong2*)&h[warp][k][0];
        #pragma unroll
        for (int i = 0; i < 16; i++) {
            ulonglong2 h2 = hp[i];
            aA0 = fma2(wA[i].x, h2.x, aA0);
            aA1 = fma2(wA[i].y, h2.y, aA1);
            aB0 = fma2(wB[i].x, h2.x, aB0);
            aB1 = fma2(wB[i].y, h2.y, aB1);
        }
        m0 = fmaxf(m0, lrelu((red2(aA0) + red2(aA1)) + bbA));
        m1 = fmaxf(m1, lrelu((red2(aB0) + red2(aB1)) + bbB));
    }
    d_feats[q * 192 + outOff + c0] = m0;
    d_feats[q * 192 + outOff + c1] = m1;
}

// ---------------- stage 3: pure gather-max (no conv) --------------------------
__global__ void __launch_bounds__(256) gather_max_kernel() {
    int t = blockIdx.x * 256 + threadIdx.x;
    int q = t >> 6, c = t & 63;
    int rowbase = q & ~4095;           // batch base
    float Cq = d_cst[q * 64 + c];
    const int* ip = d_idx + q * KK;
    float m = -3.4e38f;
    #pragma unroll 8
    for (int k = 0; k < KK; k++)
        m = fmaxf(m, lrelu(d_P[(rowbase + ip[k]) * 64 + c] + Cq));
    d_feats[q * 192 + 128 + c] = m;
}

// ---------------- tiled GEMM: C[M,N] = A[M,K] @ B[N,K]^T ----------------------
// 128x64 block tile, 256 threads, 8x4 per-thread f32x2 micro-tile,
// double-buffered smem (global prefetch overlapped with compute).
// EPI: 0 plain, 1 scale/bias/lrelu, 2 +gterm+scale/bias/lrelu,
//      3 conv6 (col-max + atomicMax), 4 conv9 (bias, transposed store),
//      5 a*s+b (affine, no lrelu), 6 a*s (scale only)
template <int EPI>
__global__ void __launch_bounds__(256) gemm_k(
    const float* __restrict__ A, int lda,
    const float* __restrict__ B, int ldb, int nrows,
    int K, float* __restrict__ C, int ldc,
    const float* __restrict__ sv, const float* __restrict__ bv) {
    __shared__ __align__(16) float As[2][128][18];
    __shared__ __align__(16) float Bs[2][64][18];
    int tid = threadIdx.x;
    int tx = tid & 15, ty = tid >> 4;
    int mBase = blockIdx.y * 128, nBase = blockIdx.x * 64;
    int lrA = tid >> 1, lcA = (tid & 1) * 8;
    int lrB = tid >> 2, lcB = (tid & 3) * 4;
    const float* Ap = A + (mBase + lrA) * lda + lcA;
    const float* Bp = B + (nBase + lrB) * ldb + lcB;
    bool bval = (nBase + lrB) < nrows;

    // load tile 0
    float4 a0 = *(const float4*)(Ap);
    float4 a1 = *(const float4*)(Ap + 4);
    float4 bw = bval ? *(const float4*)(Bp) : make_float4(0.f, 0.f, 0.f, 0.f);
    *(float2*)&As[0][lrA][lcA]     = make_float2(a0.x, a0.y);
    *(float2*)&As[0][lrA][lcA + 2] = make_float2(a0.z, a0.w);
    *(float2*)&As[0][lrA][lcA + 4] = make_float2(a1.x, a1.y);
    *(float2*)&As[0][lrA][lcA + 6] = make_float2(a1.z, a1.w);
    *(float2*)&Bs[0][lrB][lcB]     = make_float2(bw.x, bw.y);
    *(float2*)&Bs[0][lrB][lcB + 2] = make_float2(bw.z, bw.w);
    __syncthreads();

    ull acc2[8][4] = {};
    int buf = 0;
    for (int kt = 16; kt <= K; kt += 16) {
        bool has_next = kt < K;
        if (has_next) {
            a0 = *(const float4*)(Ap + kt);
            a1 = *(const float4*)(Ap + kt + 4);
            bw = bval ? *(const float4*)(Bp + kt) : make_float4(0.f, 0.f, 0.f, 0.f);
        }
        #pragma unroll
        for (int kk = 0; kk < 8; kk++) {
            ull a2[8], b2[4];
            #pragma unroll
            for (int mi = 0; mi < 8; mi++) a2[mi] = *(const ull*)&As[buf][ty + mi * 16][kk * 2];
            #pragma unroll
            for (int ni = 0; ni < 4; ni++) b2[ni] = *(const ull*)&Bs[buf][tx + ni * 16][kk * 2];
            #pragma unroll
            for (int mi = 0; mi < 8; mi++)
                #pragma unroll
                for (int ni = 0; ni < 4; ni++)
                    acc2[mi][ni] = fma2(a2[mi], b2[ni], acc2[mi][ni]);
        }
        if (has_next) {
            int nb = buf ^ 1;
            *(float2*)&As[nb][lrA][lcA]     = make_float2(a0.x, a0.y);
            *(float2*)&As[nb][lrA][lcA + 2] = make_float2(a0.z, a0.w);
            *(float2*)&As[nb][lrA][lcA + 4] = make_float2(a1.x, a1.y);
            *(float2*)&As[nb][lrA][lcA + 6] = make_float2(a1.z, a1.w);
            *(float2*)&Bs[nb][lrB][lcB]     = make_float2(bw.x, bw.y);
            *(float2*)&Bs[nb][lrB][lcB + 2] = make_float2(bw.z, bw.w);
            __syncthreads();
            buf = nb;
        }
    }

    float acc[8][4];
    #pragma unroll
    for (int mi = 0; mi < 8; mi++)
        #pragma unroll
        for (int ni = 0; ni < 4; ni++) acc[mi][ni] = red2(acc2[mi][ni]);

    if (EPI == 3) {
        int bb = mBase >> 12;
        float cm[4];
        #pragma unroll
        for (int ni = 0; ni < 4; ni++) {
            int nn = nBase + tx + ni * 16;
            float s = sv[nn], bbv = bv[nn];
            float m = -3.4e38f;
            #pragma unroll
            for (int mi = 0; mi < 8; mi++)
                m = fmaxf(m, lrelu(acc[mi][ni] * s + bbv));
            cm[ni] = m;
        }
        float* stage = &As[0][0][0];   // 16*64 floats, plenty of room
        __syncthreads();
        #pragma unroll
        for (int ni = 0; ni < 4; ni++) stage[ty * 64 + tx + ni * 16] = cm[ni];
        __syncthreads();
        if (tid < 64) {
            float m = stage[tid];
            #pragma unroll
            for (int r = 1; r < 16; r++) m = fmaxf(m, stage[r * 64 + tid]);
            atomicMax(&d_gmax[bb * 1024 + nBase + tid], fkey(m));
        }
        return;
    }

    #pragma unroll
    for (int mi = 0; mi < 8; mi++) {
        int m = mBase + ty + mi * 16;
        #pragma unroll
        for (int ni = 0; ni < 4; ni++) {
            int n = nBase + tx + ni * 16;
            float a = acc[mi][ni];
            if (EPI == 0) {
                C[m * ldc + n] = a;
            } else if (EPI == 1) {
                C[m * ldc + n] = lrelu(a * sv[n] + bv[n]);
            } else if (EPI == 2) {
                int bb = m >> 12;
                C[m * ldc + n] = lrelu((a + d_gterm[bb * 512 + n]) * sv[n] + bv[n]);
            } else if (EPI == 5) {
                C[m * ldc + n] = a * sv[n] + bv[n];
            } else if (EPI == 6) {
                C[m * ldc + n] = a * sv[n];
            } else { // EPI == 4 : conv9, transposed output (B,63,N)
                if (n < 63) {
                    int bb = m >> 12; int nn = m & 4095;
                    C[(bb * 63 + n) * 4096 + nn] = a + bv[n];
                }
            }
        }
    }
}

// ---------------- gterm: g[b] @ W7[:, :1024]^T --------------------------------
__global__ void __launch_bounds__(256) gterm_kernel(const float* __restrict__ W7) {
    int b = blockIdx.x >> 3;
    int cg = blockIdx.x & 7;   // group of 64 couts
    __shared__ float gs[1024];
    __shared__ float warpsum[8];
    int tid = threadIdx.x;
    for (int i = tid; i < 1024; i += 256) gs[i] = fdecode(d_gmax[b * 1024 + i]);
    __syncthreads();
    for (int cl = 0; cl < 64; cl++) {
        int cOut = cg * 64 + cl;
        float4 wv = ((const float4*)(W7 + cOut * 1216))[tid];
        float4 g4 = *(const float4*)&gs[tid * 4];
        float p = wv.x * g4.x + wv.y * g4.y + wv.z * g4.z + wv.w * g4.w;
        #pragma unroll
        for (int o = 16; o > 0; o >>= 1) p += __shfl_down_sync(0xffffffffu, p, o);
        if ((tid & 31) == 0) warpsum[tid >> 5] = p;
        __syncthreads();
        if (tid == 0) {
            float s = 0;
            #pragma unroll
            for (int r = 0; r < 8; r++) s += warpsum[r];
            d_gterm[b * 512 + cOut] = s;
        }
        __syncthreads();
    }
}

// ---------------- host --------------------------------------------------------
extern "C" void kernel_launch(void* const* d_in, const int* in_sizes, int n_in,
                              void* d_out, int out_size) {
    const float* x  = (const float*)d_in[0];
    const float* W1 = (const float*)d_in[1];
    const float* s1 = (const float*)d_in[2];
    const float* b1 = (const float*)d_in[3];
    const float* W2 = (const float*)d_in[4];
    const float* s2 = (const float*)d_in[5];
    const float* b2 = (const float*)d_in[6];
    const float* W3 = (const float*)d_in[7];
    const float* s3 = (const float*)d_in[8];
    const float* b3 = (const float*)d_in[9];
    const float* W4 = (const float*)d_in[10];
    const float* s4 = (const float*)d_in[11];
    const float* b4 = (const float*)d_in[12];
    const float* W5 = (const float*)d_in[13];
    const float* s5 = (const float*)d_in[14];
    const float* b5 = (const float*)d_in[15];
    const float* W6 = (const float*)d_in[16];
    const float* s6 = (const float*)d_in[17];
    const float* b6 = (const float*)d_in[18];
    const float* W7 = (const float*)d_in[19];
    const float* s7 = (const float*)d_in[20];
    const float* b7 = (const float*)d_in[21];
    const float* W8 = (const float*)d_in[22];
    const float* s8 = (const float*)d_in[23];
    const float* b8 = (const float*)d_in[24];
    const float* W9 = (const float*)d_in[25];
    const float* b9 = (const float*)d_in[26];
    float* out = (float*)d_out;

    float *feats, *cst, *P, *h7, *h8, *wd3, *wd5;
    cudaGetSymbolAddress((void**)&feats, d_feats);
    cudaGetSymbolAddress((void**)&cst,   d_cst);
    cudaGetSymbolAddress((void**)&P,     d_P);
    cudaGetSymbolAddress((void**)&h7,    d_h7);
    cudaGetSymbolAddress((void**)&h8,    d_h8);
    cudaGetSymbolAddress((void**)&wd3,   d_wd3);
    cudaGetSymbolAddress((void**)&wd5,   d_wd5);

    knn_kernel<<<BN_TOT, 128>>>(x);                             // 0
    prep1_kernel<<<4096, 256>>>(x, W1, s1, b1);                 // 1
    prep_w_kernel<<<32, 256>>>(W3, W5);                         // 2
    // stage1: gather(P1,C1) -> conv2 -> max -> x1
    edge_conv_kernel<<<BN_TOT / 2, 64>>>(W2, s2, b2, 0);        // 3  <- ncu captures this
    prep_g_kernel<<<16, 256>>>();
    // stage2 precompute: P = (x1 @ W3lo^T)*s3 ; C = (x1 @ wd3^T)*s3 + b3
    gemm_k<6><<<dim3(1, 128), 256>>>(feats, 192, W3, 128, 64, 64, P, 64, s3, nullptr);
    gemm_k<5><<<dim3(1, 128), 256>>>(feats, 192, wd3, 64, 64, 64, cst, 64, s3, b3);
    // stage2: gather -> conv4 -> max -> x2
    edge_conv_kernel<<<BN_TOT / 2, 64>>>(W4, s4, b4, 64);
    // stage3 precompute: P = (x2 @ W5lo^T)*s5 ; C = (x2 @ wd5^T)*s5 + b5
    gemm_k<6><<<dim3(1, 128), 256>>>(feats + 64, 192, W5, 128, 64, 64, P, 64, s5, nullptr);
    gemm_k<5><<<dim3(1, 128), 256>>>(feats + 64, 192, wd5, 64, 64, 64, cst, 64, s5, b5);
    // stage3: pure gather-max -> x3
    gather_max_kernel<<<4096, 256>>>();
    // conv6 + global max over N (per batch, per channel)
    gemm_k<3><<<dim3(16, 128), 256>>>(feats, 192, W6, 192, 1024, 192, nullptr, 0, s6, b6);
    // gterm[b] = g[b] @ W7[:, :1024]^T
    gterm_kernel<<<32, 256>>>(W7);
    // conv7 on feature part only (K=192) + gterm in epilogue
    gemm_k<2><<<dim3(8, 128), 256>>>(feats, 192, W7 + 1024, 1216, 512, 192, h7, 512, s7, b7);
    // conv8
    gemm_k<1><<<dim3(4, 128), 256>>>(h7, 512, W8, 512, 256, 512, h8, 256, s8, b8);
    // conv9 -> transposed output (B, 63, N)
    gemm_k<4><<<dim3(1, 128), 256>>>(h8, 256, W9, 256, 63, 256, out, 0, nullptr, b9);
}

// round 17
// speedup vs baseline: 1.7597x; 1.0191x over previous
#include <cuda_runtime.h>

#define BN_TOT 16384   // B*N = 4*4096
#define NPTS   4096
#define KK     40

typedef unsigned long long ull;

// ---------------- scratch (device globals; no allocation allowed) -------------
__device__ int      d_idx[BN_TOT * KK];
__device__ float    d_feats[BN_TOT * 192];   // [x1 | x2 | x3]
__device__ float    d_P[BN_TOT * 64];        // per-stage neighbor term (scaled)
__device__ float    d_cst[BN_TOT * 64];      // per-stage center term (affine folded)
__device__ float    d_h7[BN_TOT * 512];
__device__ float    d_h8[BN_TOT * 256];
__device__ unsigned d_gmax[4 * 1024];        // per-batch conv6 max (order-preserving uint)
__device__ float    d_wd3[64 * 64];          // W3[:,64:128]-W3[:,0:64]
__device__ float    d_wd5[64 * 64];
__device__ float    d_gterm[4 * 512];        // g @ W7[:, :1024]^T  per batch

__device__ __forceinline__ unsigned fkey(float f) {
    unsigned u = __float_as_uint(f);
    return (u & 0x80000000u) ? ~u : (u | 0x80000000u);
}
__device__ __forceinline__ float fdecode(unsigned k) {
    return (k & 0x80000000u) ? __uint_as_float(k ^ 0x80000000u) : __uint_as_float(~k);
}
__device__ __forceinline__ float lrelu(float v) { return v >= 0.f ? v : 0.2f * v; }

// packed fp32x2 FMA (Blackwell)
__device__ __forceinline__ ull fma2(ull a, ull b, ull c) {
    ull d;
    asm("fma.rn.f32x2 %0, %1, %2, %3;" : "=l"(d) : "l"(a), "l"(b), "l"(c));
    return d;
}
__device__ __forceinline__ ull mul2(ull a, ull b) {
    ull d;
    asm("mul.rn.f32x2 %0, %1, %2;" : "=l"(d) : "l"(a), "l"(b));
    return d;
}
__device__ __forceinline__ float red2(ull a) {
    float x, y;
    asm("mov.b64 {%0, %1}, %2;" : "=f"(x), "=f"(y) : "l"(a));
    return x + y;
}
__device__ __forceinline__ ull pack2(float x, float y) {
    ull d;
    asm("mov.b64 %0, {%1, %2};" : "=l"(d) : "f"(x), "f"(y));
    return d;
}

// ---------------- prep kernels ------------------------------------------------
__global__ void prep_w_kernel(const float* __restrict__ W3, const float* __restrict__ W5) {
    int t = blockIdx.x * blockDim.x + threadIdx.x;
    if (t < 4096) {
        int c = t >> 6, i = t & 63;
        d_wd3[t] = W3[c * 128 + 64 + i] - W3[c * 128 + i];
    } else if (t < 8192) {
        int u = t - 4096; int c = u >> 6, i = u & 63;
        d_wd5[u] = W5[c * 128 + 64 + i] - W5[c * 128 + i];
    }
}
__global__ void prep_g_kernel() {
    int t = blockIdx.x * blockDim.x + threadIdx.x;
    if (t < 4096) d_gmax[t] = 0u;
}

// stage1 P/C: P[q,c] = (W1lo[c]·xyz_q)*s1[c], C[q,c] = ((W1hi-W1lo)[c]·xyz_q)*s1[c]+b1[c]
__global__ void __launch_bounds__(256) prep1_kernel(
    const float* __restrict__ x, const float* __restrict__ W1,
    const float* __restrict__ s1, const float* __restrict__ b1) {
    int t = blockIdx.x * 256 + threadIdx.x;
    int q = t >> 6, c = t & 63;
    int b = q >> 12, n = q & 4095;
    const float* xb = x + b * 3 * NPTS;
    float cx = xb[n], cy = xb[NPTS + n], cz = xb[2 * NPTS + n];
    float w0 = W1[c * 6 + 0], w1 = W1[c * 6 + 1], w2 = W1[c * 6 + 2];
    float w3 = W1[c * 6 + 3], w4 = W1[c * 6 + 4], w5 = W1[c * 6 + 5];
    float s = s1[c];
    d_P[q * 64 + c]   = (w0 * cx + w1 * cy + w2 * cz) * s;
    d_cst[q * 64 + c] = ((w3 - w0) * cx + (w4 - w1) * cy + (w5 - w2) * cz) * s + b1[c];
}

// ---------------- KNN: radix top-40; match-aggregated atomics in pass 0 -------
__global__ void __launch_bounds__(128) knn_kernel(const float* __restrict__ x) {
    const int q = blockIdx.x;
    const int b = q >> 12, n = q & 4095;
    const int tid = threadIdx.x;
    __shared__ unsigned key[NPTS];
    __shared__ unsigned hist[256];
    __shared__ unsigned sc[2];
    __shared__ int cHi, cEq;

    const float* xb = x + b * 3 * NPTS;
    float cx = xb[n], cy = xb[NPTS + n], cz = xb[2 * NPTS + n];
    float xxi = cx * cx + cy * cy + cz * cz;

    for (int j = tid; j < NPTS; j += 128) {
        float px = xb[j], py = xb[NPTS + j], pz = xb[2 * NPTS + j];
        float dot = cx * px + cy * py + cz * pz;
        float xxj = px * px + py * py + pz * pz;
        float d = (2.f * dot - xxi) - xxj;   // = -||xi-xj||^2, larger = nearer
        key[j] = fkey(d);
    }

    unsigned prefix = 0, need = KK;
    for (int pass = 0; pass < 4; ++pass) {
        int shift = 24 - 8 * pass;
        unsigned himask = (pass == 0) ? 0u : (0xFFFFFFFFu << (shift + 8));
        for (int i2 = tid; i2 < 256; i2 += 128) hist[i2] = 0u;
        __syncthreads();
        if (pass == 0) {
            for (int j = tid; j < NPTS; j += 128) {
                int bucket = (int)(key[j] >> shift);
                unsigned mm = __match_any_sync(0xffffffffu, bucket);
                if ((tid & 31) == (__ffs(mm) - 1))
                    atomicAdd(&hist[bucket], (unsigned)__popc(mm));
            }
        } else {
            for (int j = tid; j < NPTS; j += 128) {
                unsigned k = key[j];
                if ((k & himask) == (prefix & himask))
                    atomicAdd(&hist[(k >> shift) & 255], 1u);
            }
        }
        __syncthreads();
        if (tid < 32) {
            unsigned part[8]; unsigned s = 0;
            #pragma unroll
            for (int r = 0; r < 8; r++) { part[r] = hist[255 - tid * 8 - r]; s += part[r]; }
            unsigned inc = s;
            #pragma unroll
            for (int o = 1; o < 32; o <<= 1) {
                unsigned v = __shfl_up_sync(0xffffffffu, inc, o);
                if (tid >= o) inc += v;
            }
            unsigned excl = inc - s;
            unsigned ball = __ballot_sync(0xffffffffu, (excl < need) && (need <= inc));
            int lane = __ffs(ball) - 1;
            if (tid == lane) {
                unsigned rem = need - excl, cacc = 0; int r = 0;
                for (; r < 8; r++) { if (cacc + part[r] >= rem) break; cacc += part[r]; }
                unsigned v = 255u - (unsigned)(tid * 8) - (unsigned)r;
                sc[0] = prefix | (v << shift);
                sc[1] = rem - cacc;
            }
        }
        __syncthreads();
        prefix = sc[0]; need = sc[1];
        __syncthreads();
    }

    if (tid == 0) { cHi = 0; cEq = 0; }
    __syncthreads();
    int base = q * KK;
    int takeEq = (int)need;
    int nAbove = KK - takeEq;
    for (int j = tid; j < NPTS; j += 128) {
        unsigned k = key[j];
        if (k > prefix) {
            int p = atomicAdd(&cHi, 1);
            d_idx[base + p] = j;
        } else if (k == prefix) {
            int p = atomicAdd(&cEq, 1);
            if (p < takeEq) d_idx[base + nAbove + p] = j;
        }
    }
}

// ---------------- edge conv: gather(P,C)->lrelu->conv(W)->max -----------------
// ONE WARP per point (2 points / 64-thread block); lane owns ADJACENT channels
// (2*lane, 2*lane+1): gather/store are single float2 ops; each broadcast h-row
// read feeds 64 fma2 (2x reuse). Weights premultiplied by s.
__global__ void __launch_bounds__(64) edge_conv_kernel(
    const float* __restrict__ W, const float* __restrict__ sv, const float* __restrict__ bv,
    int outOff) {
    int warp = threadIdx.x >> 5, lane = threadIdx.x & 31;
    int q = blockIdx.x * 2 + warp;
    int c0 = lane * 2, c1 = lane * 2 + 1;
    int rowbase = q & ~4095;           // batch base: d_idx holds within-batch indices
    __shared__ __align__(16) float h[2][KK][64];
    __shared__ int sj[2][KK];
    for (int k = lane; k < KK; k += 32) sj[warp][k] = d_idx[q * KK + k];
    __syncwarp();
    float2 Cv = *(const float2*)&d_cst[q * 64 + c0];
    #pragma unroll 4
    for (int k = 0; k < KK; k++) {
        float2 pv = *(const float2*)(d_P + (rowbase + sj[warp][k]) * 64 + c0);
        *(float2*)&h[warp][k][c0] = make_float2(lrelu(pv.x + Cv.x), lrelu(pv.y + Cv.y));
    }
    float2 sv2 = *(const float2*)&sv[c0];
    float2 bv2 = *(const float2*)&bv[c0];
    float bbA = bv2.x, bbB = bv2.y;
    ull sA2 = pack2(sv2.x, sv2.x), sB2 = pack2(sv2.y, sv2.y);
    ulonglong2 wA[16], wB[16];
    #pragma unroll
    for (int i = 0; i < 16; i++) {
        ulonglong2 wr = ((const ulonglong2*)(W + c0 * 64))[i];
        wA[i].x = mul2(wr.x, sA2);
        wA[i].y = mul2(wr.y, sA2);
    }
    #pragma unroll
    for (int i = 0; i < 16; i++) {
        ulonglong2 wr = ((const ulonglong2*)(W + c1 * 64))[i];
        wB[i].x = mul2(wr.x, sB2);
        wB[i].y = mul2(wr.y, sB2);
    }
    __syncwarp();
    float m0 = -3.4e38f, m1 = -3.4e38f;
    for (int k = 0; k < KK; k++) {
        ull aA0 = 0ULL, aA1 = 0ULL, aB0 = 0ULL, aB1 = 0ULL;
        const ulonglong2* hp = (const ulonglong2*)&h[warp][k][0];
        #pragma unroll
        for (int i = 0; i < 16; i++) {
            ulonglong2 h2 = hp[i];
            aA0 = fma2(wA[i].x, h2.x, aA0);
            aA1 = fma2(wA[i].y, h2.y, aA1);
            aB0 = fma2(wB[i].x, h2.x, aB0);
            aB1 = fma2(wB[i].y, h2.y, aB1);
        }
        m0 = fmaxf(m0, lrelu((red2(aA0) + red2(aA1)) + bbA));
        m1 = fmaxf(m1, lrelu((red2(aB0) + red2(aB1)) + bbB));
    }
    *(float2*)&d_feats[q * 192 + outOff + c0] = make_float2(m0, m1);
}

// ---------------- stage 3: pure gather-max (no conv) --------------------------
// thread owns adjacent channel pair -> float2 gathers/stores
__global__ void __launch_bounds__(256) gather_max_kernel() {
    int t = blockIdx.x * 256 + threadIdx.x;
    int q = t >> 5, c0 = (t & 31) * 2;
    int rowbase = q & ~4095;           // batch base
    float2 Cv = *(const float2*)&d_cst[q * 64 + c0];
    const int* ip = d_idx + q * KK;
    float m0 = -3.4e38f, m1 = -3.4e38f;
    #pragma unroll 8
    for (int k = 0; k < KK; k++) {
        float2 pv = *(const float2*)(d_P + (rowbase + ip[k]) * 64 + c0);
        m0 = fmaxf(m0, lrelu(pv.x + Cv.x));
        m1 = fmaxf(m1, lrelu(pv.y + Cv.y));
    }
    *(float2*)&d_feats[q * 192 + 128 + c0] = make_float2(m0, m1);
}

// ---------------- tiled GEMM: C[M,N] = A[M,K] @ B[N,K]^T ----------------------
// 128x64 block tile, 256 threads, 8x4 per-thread f32x2 micro-tile,
// double-buffered smem (global prefetch overlapped with compute).
// EPI: 0 plain, 1 scale/bias/lrelu, 2 +gterm+scale/bias/lrelu,
//      3 conv6 (col-max + atomicMax), 4 conv9 (bias, transposed store),
//      5 a*s+b (affine, no lrelu), 6 a*s (scale only)
template <int EPI>
__global__ void __launch_bounds__(256) gemm_k(
    const float* __restrict__ A, int lda,
    const float* __restrict__ B, int ldb, int nrows,
    int K, float* __restrict__ C, int ldc,
    const float* __restrict__ sv, const float* __restrict__ bv) {
    __shared__ __align__(16) float As[2][128][18];
    __shared__ __align__(16) float Bs[2][64][18];
    int tid = threadIdx.x;
    int tx = tid & 15, ty = tid >> 4;
    int mBase = blockIdx.y * 128, nBase = blockIdx.x * 64;
    int lrA = tid >> 1, lcA = (tid & 1) * 8;
    int lrB = tid >> 2, lcB = (tid & 3) * 4;
    const float* Ap = A + (mBase + lrA) * lda + lcA;
    const float* Bp = B + (nBase + lrB) * ldb + lcB;
    bool bval = (nBase + lrB) < nrows;

    // load tile 0
    float4 a0 = *(const float4*)(Ap);
    float4 a1 = *(const float4*)(Ap + 4);
    float4 bw = bval ? *(const float4*)(Bp) : make_float4(0.f, 0.f, 0.f, 0.f);
    *(float2*)&As[0][lrA][lcA]     = make_float2(a0.x, a0.y);
    *(float2*)&As[0][lrA][lcA + 2] = make_float2(a0.z, a0.w);
    *(float2*)&As[0][lrA][lcA + 4] = make_float2(a1.x, a1.y);
    *(float2*)&As[0][lrA][lcA + 6] = make_float2(a1.z, a1.w);
    *(float2*)&Bs[0][lrB][lcB]     = make_float2(bw.x, bw.y);
    *(float2*)&Bs[0][lrB][lcB + 2] = make_float2(bw.z, bw.w);
    __syncthreads();

    ull acc2[8][4] = {};
    int buf = 0;
    for (int kt = 16; kt <= K; kt += 16) {
        bool has_next = kt < K;
        if (has_next) {
            a0 = *(const float4*)(Ap + kt);
            a1 = *(const float4*)(Ap + kt + 4);
            bw = bval ? *(const float4*)(Bp + kt) : make_float4(0.f, 0.f, 0.f, 0.f);
        }
        #pragma unroll
        for (int kk = 0; kk < 8; kk++) {
            ull a2[8], b2[4];
            #pragma unroll
            for (int mi = 0; mi < 8; mi++) a2[mi] = *(const ull*)&As[buf][ty + mi * 16][kk * 2];
            #pragma unroll
            for (int ni = 0; ni < 4; ni++) b2[ni] = *(const ull*)&Bs[buf][tx + ni * 16][kk * 2];
            #pragma unroll
            for (int mi = 0; mi < 8; mi++)
                #pragma unroll
                for (int ni = 0; ni < 4; ni++)
                    acc2[mi][ni] = fma2(a2[mi], b2[ni], acc2[mi][ni]);
        }
        if (has_next) {
            int nb = buf ^ 1;
            *(float2*)&As[nb][lrA][lcA]     = make_float2(a0.x, a0.y);
            *(float2*)&As[nb][lrA][lcA + 2] = make_float2(a0.z, a0.w);
            *(float2*)&As[nb][lrA][lcA + 4] = make_float2(a1.x, a1.y);
            *(float2*)&As[nb][lrA][lcA + 6] = make_float2(a1.z, a1.w);
            *(float2*)&Bs[nb][lrB][lcB]     = make_float2(bw.x, bw.y);
            *(float2*)&Bs[nb][lrB][lcB + 2] = make_float2(bw.z, bw.w);
            __syncthreads();
            buf = nb;
        }
    }

    float acc[8][4];
    #pragma unroll
    for (int mi = 0; mi < 8; mi++)
        #pragma unroll
        for (int ni = 0; ni < 4; ni++) acc[mi][ni] = red2(acc2[mi][ni]);

    if (EPI == 3) {
        int bb = mBase >> 12;
        float cm[4];
        #pragma unroll
        for (int ni = 0; ni < 4; ni++) {
            int nn = nBase + tx + ni * 16;
            float s = sv[nn], bbv = bv[nn];
            float m = -3.4e38f;
            #pragma unroll
            for (int mi = 0; mi < 8; mi++)
                m = fmaxf(m, lrelu(acc[mi][ni] * s + bbv));
            cm[ni] = m;
        }
        float* stage = &As[0][0][0];   // 16*64 floats, plenty of room
        __syncthreads();
        #pragma unroll
        for (int ni = 0; ni < 4; ni++) stage[ty * 64 + tx + ni * 16] = cm[ni];
        __syncthreads();
        if (tid < 64) {
            float m = stage[tid];
            #pragma unroll
            for (int r = 1; r < 16; r++) m = fmaxf(m, stage[r * 64 + tid]);
            atomicMax(&d_gmax[bb * 1024 + nBase + tid], fkey(m));
        }
        return;
    }

    #pragma unroll
    for (int mi = 0; mi < 8; mi++) {
        int m = mBase + ty + mi * 16;
        #pragma unroll
        for (int ni = 0; ni < 4; ni++) {
            int n = nBase + tx + ni * 16;
            float a = acc[mi][ni];
            if (EPI == 0) {
                C[m * ldc + n] = a;
            } else if (EPI == 1) {
                C[m * ldc + n] = lrelu(a * sv[n] + bv[n]);
            } else if (EPI == 2) {
                int bb = m >> 12;
                C[m * ldc + n] = lrelu((a + d_gterm[bb * 512 + n]) * sv[n] + bv[n]);
            } else if (EPI == 5) {
                C[m * ldc + n] = a * sv[n] + bv[n];
            } else if (EPI == 6) {
                C[m * ldc + n] = a * sv[n];
            } else { // EPI == 4 : conv9, transposed output (B,63,N)
                if (n < 63) {
                    int bb = m >> 12; int nn = m & 4095;
                    C[(bb * 63 + n) * 4096 + nn] = a + bv[n];
                }
            }
        }
    }
}

// ---------------- gterm: g[b] @ W7[:, :1024]^T --------------------------------
__global__ void __launch_bounds__(256) gterm_kernel(const float* __restrict__ W7) {
    int b = blockIdx.x >> 3;
    int cg = blockIdx.x & 7;   // group of 64 couts
    __shared__ float gs[1024];
    __shared__ float warpsum[8];
    int tid = threadIdx.x;
    for (int i = tid; i < 1024; i += 256) gs[i] = fdecode(d_gmax[b * 1024 + i]);
    __syncthreads();
    for (int cl = 0; cl < 64; cl++) {
        int cOut = cg * 64 + cl;
        float4 wv = ((const float4*)(W7 + cOut * 1216))[tid];
        float4 g4 = *(const float4*)&gs[tid * 4];
        float p = wv.x * g4.x + wv.y * g4.y + wv.z * g4.z + wv.w * g4.w;
        #pragma unroll
        for (int o = 16; o > 0; o >>= 1) p += __shfl_down_sync(0xffffffffu, p, o);
        if ((tid & 31) == 0) warpsum[tid >> 5] = p;
        __syncthreads();
        if (tid == 0) {
            float s = 0;
            #pragma unroll
            for (int r = 0; r < 8; r++) s += warpsum[r];
            d_gterm[b * 512 + cOut] = s;
        }
        __syncthreads();
    }
}

// ---------------- host --------------------------------------------------------
extern "C" void kernel_launch(void* const* d_in, const int* in_sizes, int n_in,
                              void* d_out, int out_size) {
    const float* x  = (const float*)d_in[0];
    const float* W1 = (const float*)d_in[1];
    const float* s1 = (const float*)d_in[2];
    const float* b1 = (const float*)d_in[3];
    const float* W2 = (const float*)d_in[4];
    const float* s2 = (const float*)d_in[5];
    const float* b2 = (const float*)d_in[6];
    const float* W3 = (const float*)d_in[7];
    const float* s3 = (const float*)d_in[8];
    const float* b3 = (const float*)d_in[9];
    const float* W4 = (const float*)d_in[10];
    const float* s4 = (const float*)d_in[11];
    const float* b4 = (const float*)d_in[12];
    const float* W5 = (const float*)d_in[13];
    const float* s5 = (const float*)d_in[14];
    const float* b5 = (const float*)d_in[15];
    const float* W6 = (const float*)d_in[16];
    const float* s6 = (const float*)d_in[17];
    const float* b6 = (const float*)d_in[18];
    const float* W7 = (const float*)d_in[19];
    const float* s7 = (const float*)d_in[20];
    const float* b7 = (const float*)d_in[21];
    const float* W8 = (const float*)d_in[22];
    const float* s8 = (const float*)d_in[23];
    const float* b8 = (const float*)d_in[24];
    const float* W9 = (const float*)d_in[25];
    const float* b9 = (const float*)d_in[26];
    float* out = (float*)d_out;

    float *feats, *cst, *P, *h7, *h8, *wd3, *wd5;
    cudaGetSymbolAddress((void**)&feats, d_feats);
    cudaGetSymbolAddress((void**)&cst,   d_cst);
    cudaGetSymbolAddress((void**)&P,     d_P);
    cudaGetSymbolAddress((void**)&h7,    d_h7);
    cudaGetSymbolAddress((void**)&h8,    d_h8);
    cudaGetSymbolAddress((void**)&wd3,   d_wd3);
    cudaGetSymbolAddress((void**)&wd5,   d_wd5);

    knn_kernel<<<BN_TOT, 128>>>(x);                             // 0
    prep1_kernel<<<4096, 256>>>(x, W1, s1, b1);                 // 1
    prep_w_kernel<<<32, 256>>>(W3, W5);                         // 2
    // stage1: gather(P1,C1) -> conv2 -> max -> x1
    edge_conv_kernel<<<BN_TOT / 2, 64>>>(W2, s2, b2, 0);        // 3  <- ncu captures this
    prep_g_kernel<<<16, 256>>>();
    // stage2 precompute: P = (x1 @ W3lo^T)*s3 ; C = (x1 @ wd3^T)*s3 + b3
    gemm_k<6><<<dim3(1, 128), 256>>>(feats, 192, W3, 128, 64, 64, P, 64, s3, nullptr);
    gemm_k<5><<<dim3(1, 128), 256>>>(feats, 192, wd3, 64, 64, 64, cst, 64, s3, b3);
    // stage2: gather -> conv4 -> max -> x2
    edge_conv_kernel<<<BN_TOT / 2, 64>>>(W4, s4, b4, 64);
    // stage3 precompute: P = (x2 @ W5lo^T)*s5 ; C = (x2 @ wd5^T)*s5 + b5
    gemm_k<6><<<dim3(1, 128), 256>>>(feats + 64, 192, W5, 128, 64, 64, P, 64, s5, nullptr);
    gemm_k<5><<<dim3(1, 128), 256>>>(feats + 64, 192, wd5, 64, 64, 64, cst, 64, s5, b5);
    // stage3: pure gather-max -> x3
    gather_max_kernel<<<2048, 256>>>();
    // conv6 + global max over N (per batch, per channel)
    gemm_k<3><<<dim3(16, 128), 256>>>(feats, 192, W6, 192, 1024, 192, nullptr, 0, s6, b6);
    // gterm[b] = g[b] @ W7[:, :1024]^T
    gterm_kernel<<<32, 256>>>(W7);
    // conv7 on feature part only (K=192) + gterm in epilogue
    gemm_k<2><<<dim3(8, 128), 256>>>(feats, 192, W7 + 1024, 1216, 512, 192, h7, 512, s7, b7);
    // conv8
    gemm_k<1><<<dim3(4, 128), 256>>>(h7, 512, W8, 512, 256, 512, h8, 256, s8, b8);
    // conv9 -> transposed output (B, 63, N)
    gemm_k<4><<<dim3(1, 128), 256>>>(h8, 256, W9, 256, 63, 256, out, 0, nullptr, b9);
}